// round 1
// baseline (speedup 1.0000x reference)
#include <cuda_runtime.h>
#include <math.h>

// Problem constants
#define BB   4
#define SS   1024
#define HID  1024
#define NH   32
#define HD   32
#define MAXP 1024
#define SCALE 0.17677669529663688f   // 1/sqrt(32)

// Scratch (device globals: allocation-free rule)
__device__ float g_q[BB * NH * SS * HD];
__device__ float g_k[BB * NH * SS * HD];
__device__ float g_v[BB * NH * SS * HD];
__device__ float g_ctx[BB * NH * SS * HD];

// ---------------------------------------------------------------------------
// SGEMM: C[m,n] = sum_k A[m,k]*W[n,k] + bias[n]   (M=4096, N=1024, K=1024)
// Output scattered into (b,h,s,d) layout for Q/K/V.
// BM=BN=128, BK=16, 256 threads, 8x8 per thread.
// ---------------------------------------------------------------------------
__global__ __launch_bounds__(256, 2) void sgemm_qkv(
    const float* __restrict__ A, const float* __restrict__ W,
    const float* __restrict__ bias, int sel)
{
    float* out = (sel == 0) ? g_q : (sel == 1) ? g_k : g_v;
    const int tid = threadIdx.x;
    const int tr = tid >> 4;      // 0..15
    const int tc = tid & 15;      // 0..15
    const int row0 = blockIdx.y * 128;
    const int col0 = blockIdx.x * 128;

    __shared__ float As[16][132];
    __shared__ float Bs[16][132];

    float acc[8][8];
#pragma unroll
    for (int i = 0; i < 8; i++)
#pragma unroll
        for (int j = 0; j < 8; j++) acc[i][j] = 0.f;

    for (int k0 = 0; k0 < 1024; k0 += 16) {
#pragma unroll
        for (int it = 0; it < 2; ++it) {
            int lin = tid + it * 256;        // 512 float4 per tile
            int m = lin >> 2;
            int k4 = (lin & 3) * 4;
            float4 av = *(const float4*)(A + (size_t)(row0 + m) * 1024 + k0 + k4);
            As[k4 + 0][m] = av.x; As[k4 + 1][m] = av.y;
            As[k4 + 2][m] = av.z; As[k4 + 3][m] = av.w;
            float4 bv = *(const float4*)(W + (size_t)(col0 + m) * 1024 + k0 + k4);
            Bs[k4 + 0][m] = bv.x; Bs[k4 + 1][m] = bv.y;
            Bs[k4 + 2][m] = bv.z; Bs[k4 + 3][m] = bv.w;
        }
        __syncthreads();
#pragma unroll
        for (int dd = 0; dd < 16; ++dd) {
            float a[8], bb[8];
            *(float4*)(a)     = *(float4*)&As[dd][tr * 8];
            *(float4*)(a + 4) = *(float4*)&As[dd][tr * 8 + 4];
            *(float4*)(bb)     = *(float4*)&Bs[dd][tc * 8];
            *(float4*)(bb + 4) = *(float4*)&Bs[dd][tc * 8 + 4];
#pragma unroll
            for (int i = 0; i < 8; i++)
#pragma unroll
                for (int j = 0; j < 8; j++) acc[i][j] = fmaf(a[i], bb[j], acc[i][j]);
        }
        __syncthreads();
    }

#pragma unroll
    for (int i = 0; i < 8; i++) {
        int m = row0 + tr * 8 + i;
        int b_ = m >> 10, s = m & 1023;
#pragma unroll
        for (int j = 0; j < 8; j++) {
            int n = col0 + tc * 8 + j;
            int h = n >> 5, d = n & 31;
            out[((((size_t)b_ * NH + h) << 10) + s) * HD + d] = acc[i][j] + bias[n];
        }
    }
}

// ---------------------------------------------------------------------------
// Output projection + residual: x = ctx @ Wo^T + bo + hidden  -> d_out (pre-LN)
// ctx gathered from (b,h,s,d) layout.
// ---------------------------------------------------------------------------
__global__ __launch_bounds__(256, 2) void sgemm_proj(
    const float* __restrict__ hidden, const float* __restrict__ Wo,
    const float* __restrict__ bo, float* __restrict__ out)
{
    const int tid = threadIdx.x;
    const int tr = tid >> 4;
    const int tc = tid & 15;
    const int row0 = blockIdx.y * 128;
    const int col0 = blockIdx.x * 128;

    __shared__ float As[16][132];
    __shared__ float Bs[16][132];

    float acc[8][8];
#pragma unroll
    for (int i = 0; i < 8; i++)
#pragma unroll
        for (int j = 0; j < 8; j++) acc[i][j] = 0.f;

    for (int k0 = 0; k0 < 1024; k0 += 16) {
#pragma unroll
        for (int it = 0; it < 2; ++it) {
            int lin = tid + it * 256;
            int m = lin >> 2;
            int k4 = (lin & 3) * 4;
            int kk = k0 + k4;
            int mrow = row0 + m;
            int b_ = mrow >> 10, s = mrow & 1023;
            int h = kk >> 5, dl = kk & 31;
            float4 av = *(const float4*)(g_ctx + ((((size_t)b_ * NH + h) << 10) + s) * HD + dl);
            As[k4 + 0][m] = av.x; As[k4 + 1][m] = av.y;
            As[k4 + 2][m] = av.z; As[k4 + 3][m] = av.w;
            float4 bv = *(const float4*)(Wo + (size_t)(col0 + m) * 1024 + kk);
            Bs[k4 + 0][m] = bv.x; Bs[k4 + 1][m] = bv.y;
            Bs[k4 + 2][m] = bv.z; Bs[k4 + 3][m] = bv.w;
        }
        __syncthreads();
#pragma unroll
        for (int dd = 0; dd < 16; ++dd) {
            float a[8], bb[8];
            *(float4*)(a)     = *(float4*)&As[dd][tr * 8];
            *(float4*)(a + 4) = *(float4*)&As[dd][tr * 8 + 4];
            *(float4*)(bb)     = *(float4*)&Bs[dd][tc * 8];
            *(float4*)(bb + 4) = *(float4*)&Bs[dd][tc * 8 + 4];
#pragma unroll
            for (int i = 0; i < 8; i++)
#pragma unroll
                for (int j = 0; j < 8; j++) acc[i][j] = fmaf(a[i], bb[j], acc[i][j]);
        }
        __syncthreads();
    }

#pragma unroll
    for (int i = 0; i < 8; i++) {
        int m = row0 + tr * 8 + i;
#pragma unroll
        for (int j = 0; j < 8; j++) {
            int n = col0 + tc * 8 + j;
            size_t idx = (size_t)m * 1024 + n;
            out[idx] = acc[i][j] + bo[n] + hidden[idx];
        }
    }
}

// ---------------------------------------------------------------------------
// Fused attention: per block (q-tile of 32, head h, batch b):
//   scores = (Q K^T + bias)/sqrt(HD); softmax; write probs; ctx = P V
// Scores tile (32x1024) resident in shared memory.
// ---------------------------------------------------------------------------
#define SC_STRIDE 1028
#define OFF_QST   (32 * SC_STRIDE)          // 32896
#define OFF_KV    (OFF_QST + 32 * 36)       // 34048
#define OFF_BIAS  (OFF_KV + 128 * 36)       // 38656
#define OFF_PART  (OFF_BIAS + 1056)         // 39712
#define SMEM_FLOATS (OFF_PART + 4096)       // 43808
#define SMEM_BYTES  (SMEM_FLOATS * 4)       // 175232

__global__ __launch_bounds__(256, 1) void attn_kernel(
    const float* __restrict__ dist_emb, float* __restrict__ probs_out)
{
    extern __shared__ float sm[];
    float* sc    = sm;
    float* Qst   = sm + OFF_QST;   // [d][q], stride 36
    float* KV    = sm + OFF_KV;    // [k][d], stride 36
    float* biasr = sm + OFF_BIAS;  // 1055 entries
    float* part  = sm + OFF_PART;  // [4][32][32]

    const int tid = threadIdx.x;
    const int q0 = blockIdx.x * 32;
    const int h  = blockIdx.y;
    const int b  = blockIdx.z;
    const int bh = b * NH + h;

    const float* Qg = g_q + ((size_t)bh * SS + q0) * HD;
    const float* Kg = g_k + (size_t)bh * SS * HD;
    const float* Vg = g_v + (size_t)bh * SS * HD;
    float* ctxg = g_ctx + ((size_t)bh * SS + q0) * HD;
    const size_t probs_base = ((size_t)bh * SS + q0) * SS;

    // Load Q tile transposed: Qst[d][q]
    {
        int r = tid >> 3;            // 0..31 (q row)
        int c4 = (tid & 7) * 4;      // d offset
        float4 qv = *(const float4*)(Qg + (size_t)r * HD + c4);
        Qst[(c4 + 0) * 36 + r] = qv.x; Qst[(c4 + 1) * 36 + r] = qv.y;
        Qst[(c4 + 2) * 36 + r] = qv.z; Qst[(c4 + 3) * 36 + r] = qv.w;
    }
    // Bias row: biasr[u-q0] = dist_emb[u*HD + h], u in [q0, q0+1054]
    for (int t = tid; t < 1055; t += 256)
        biasr[t] = dist_emb[(size_t)(q0 + t) * HD + h];
    __syncthreads();

    // ---- Phase A: scores ----
    const int kg = tid >> 3;   // 0..31 -> k group of 4
    const int qg = tid & 7;    // 0..7  -> q group of 4
    for (int kc = 0; kc < 8; ++kc) {
        // load K chunk [128][32] -> KV (row stride 36)
#pragma unroll
        for (int it = 0; it < 4; ++it) {
            int lin = tid + it * 256;    // 1024 float4
            int k = lin >> 3;
            int c4 = (lin & 7);
            float4 v = *(const float4*)(Kg + ((size_t)kc * 128 + k) * HD + c4 * 4);
            *(float4*)&KV[k * 36 + c4 * 4] = v;
        }
        __syncthreads();

        float acc[4][4];
#pragma unroll
        for (int i = 0; i < 4; i++)
#pragma unroll
            for (int j = 0; j < 4; j++) acc[i][j] = 0.f;

#pragma unroll
        for (int d = 0; d < 32; ++d) {
            float a0 = KV[(4 * kg + 0) * 36 + d];
            float a1 = KV[(4 * kg + 1) * 36 + d];
            float a2 = KV[(4 * kg + 2) * 36 + d];
            float a3 = KV[(4 * kg + 3) * 36 + d];
            float4 qv = *(float4*)&Qst[d * 36 + 4 * qg];
            acc[0][0] = fmaf(a0, qv.x, acc[0][0]); acc[0][1] = fmaf(a0, qv.y, acc[0][1]);
            acc[0][2] = fmaf(a0, qv.z, acc[0][2]); acc[0][3] = fmaf(a0, qv.w, acc[0][3]);
            acc[1][0] = fmaf(a1, qv.x, acc[1][0]); acc[1][1] = fmaf(a1, qv.y, acc[1][1]);
            acc[1][2] = fmaf(a1, qv.z, acc[1][2]); acc[1][3] = fmaf(a1, qv.w, acc[1][3]);
            acc[2][0] = fmaf(a2, qv.x, acc[2][0]); acc[2][1] = fmaf(a2, qv.y, acc[2][1]);
            acc[2][2] = fmaf(a2, qv.z, acc[2][2]); acc[2][3] = fmaf(a2, qv.w, acc[2][3]);
            acc[3][0] = fmaf(a3, qv.x, acc[3][0]); acc[3][1] = fmaf(a3, qv.y, acc[3][1]);
            acc[3][2] = fmaf(a3, qv.z, acc[3][2]); acc[3][3] = fmaf(a3, qv.w, acc[3][3]);
        }
#pragma unroll
        for (int i = 0; i < 4; i++) {
            int ka = kc * 128 + 4 * kg + i;
#pragma unroll
            for (int j = 0; j < 4; j++) {
                int ql = 4 * qg + j;
                sc[ql * SC_STRIDE + ka] = (acc[i][j] + biasr[ql - ka + 1023]) * SCALE;
            }
        }
        __syncthreads();
    }

    // ---- Softmax + probs write ----
    {
        int w = tid >> 5, l = tid & 31;
#pragma unroll
        for (int qi = 0; qi < 4; ++qi) {
            int q = w + 8 * qi;
            float* row = sc + q * SC_STRIDE;
            float m = -1e30f;
#pragma unroll
            for (int j = 0; j < 32; j++) m = fmaxf(m, row[l + 32 * j]);
#pragma unroll
            for (int off = 16; off > 0; off >>= 1)
                m = fmaxf(m, __shfl_xor_sync(0xffffffffu, m, off));
            float s = 0.f;
#pragma unroll
            for (int j = 0; j < 32; j++) {
                float e = __expf(row[l + 32 * j] - m);
                row[l + 32 * j] = e;
                s += e;
            }
#pragma unroll
            for (int off = 16; off > 0; off >>= 1)
                s += __shfl_xor_sync(0xffffffffu, s, off);
            float inv = 1.f / s;
            float* pg = probs_out + probs_base + (size_t)q * SS;
#pragma unroll
            for (int j = 0; j < 32; j++) {
                float p = row[l + 32 * j] * inv;
                row[l + 32 * j] = p;
                pg[l + 32 * j] = p;
            }
        }
    }
    __syncthreads();

    // ---- ctx = P @ V ----
    {
        const int g  = tid >> 6;        // 0..3 split-k group
        const int u  = tid & 63;
        const int qb = (u >> 3) * 4;    // 0,4,...,28
        const int db = (u & 7) * 4;     // 0,4,...,28
        float ca[4][4];
#pragma unroll
        for (int i = 0; i < 4; i++)
#pragma unroll
            for (int j = 0; j < 4; j++) ca[i][j] = 0.f;

        for (int kc = 0; kc < 8; ++kc) {
#pragma unroll
            for (int it = 0; it < 4; ++it) {
                int lin = tid + it * 256;
                int k = lin >> 3;
                int c4 = (lin & 7);
                float4 v = *(const float4*)(Vg + ((size_t)kc * 128 + k) * HD + c4 * 4);
                *(float4*)&KV[k * 36 + c4 * 4] = v;
            }
            __syncthreads();
#pragma unroll
            for (int kk = 0; kk < 32; ++kk) {
                int kl = g * 32 + kk;
                int col = kc * 128 + kl;
                float4 vv = *(float4*)&KV[kl * 36 + db];
                float p0 = sc[(qb + 0) * SC_STRIDE + col];
                float p1 = sc[(qb + 1) * SC_STRIDE + col];
                float p2 = sc[(qb + 2) * SC_STRIDE + col];
                float p3 = sc[(qb + 3) * SC_STRIDE + col];
                ca[0][0] = fmaf(p0, vv.x, ca[0][0]); ca[0][1] = fmaf(p0, vv.y, ca[0][1]);
                ca[0][2] = fmaf(p0, vv.z, ca[0][2]); ca[0][3] = fmaf(p0, vv.w, ca[0][3]);
                ca[1][0] = fmaf(p1, vv.x, ca[1][0]); ca[1][1] = fmaf(p1, vv.y, ca[1][1]);
                ca[1][2] = fmaf(p1, vv.z, ca[1][2]); ca[1][3] = fmaf(p1, vv.w, ca[1][3]);
                ca[2][0] = fmaf(p2, vv.x, ca[2][0]); ca[2][1] = fmaf(p2, vv.y, ca[2][1]);
                ca[2][2] = fmaf(p2, vv.z, ca[2][2]); ca[2][3] = fmaf(p2, vv.w, ca[2][3]);
                ca[3][0] = fmaf(p3, vv.x, ca[3][0]); ca[3][1] = fmaf(p3, vv.y, ca[3][1]);
                ca[3][2] = fmaf(p3, vv.z, ca[3][2]); ca[3][3] = fmaf(p3, vv.w, ca[3][3]);
            }
            __syncthreads();
        }
        // reduce across 4 split-k groups
#pragma unroll
        for (int i = 0; i < 4; i++)
#pragma unroll
            for (int j = 0; j < 4; j++)
                part[g * 1024 + (qb + i) * 32 + (db + j)] = ca[i][j];
        __syncthreads();
#pragma unroll
        for (int z = 0; z < 4; z++) {
            int o = tid * 4 + z;
            float sum = part[o] + part[1024 + o] + part[2048 + o] + part[3072 + o];
            ctxg[o] = sum;
        }
    }
}

// ---------------------------------------------------------------------------
// LayerNorm in place on d_out rows (4096 rows x 1024)
// ---------------------------------------------------------------------------
__global__ __launch_bounds__(256) void ln_kernel(
    float* __restrict__ x, const float* __restrict__ gamma,
    const float* __restrict__ beta)
{
    __shared__ float red[16];
    const int row = blockIdx.x;
    const int tid = threadIdx.x;
    float* r = x + (size_t)row * 1024;
    float4 v = *(float4*)(r + tid * 4);
    float s = v.x + v.y + v.z + v.w;
    float sq = v.x * v.x + v.y * v.y + v.z * v.z + v.w * v.w;
#pragma unroll
    for (int off = 16; off > 0; off >>= 1) {
        s  += __shfl_xor_sync(0xffffffffu, s, off);
        sq += __shfl_xor_sync(0xffffffffu, sq, off);
    }
    int w = tid >> 5, l = tid & 31;
    if (l == 0) { red[w] = s; red[8 + w] = sq; }
    __syncthreads();
    if (tid < 32) {
        float a = (tid < 8) ? red[tid] : 0.f;
        float bsq = (tid < 8) ? red[8 + tid] : 0.f;
#pragma unroll
        for (int off = 4; off > 0; off >>= 1) {
            a += __shfl_xor_sync(0xffffffffu, a, off);
            bsq += __shfl_xor_sync(0xffffffffu, bsq, off);
        }
        if (tid == 0) { red[0] = a; red[8] = bsq; }
    }
    __syncthreads();
    float mean = red[0] * (1.f / 1024.f);
    float var = red[8] * (1.f / 1024.f) - mean * mean;
    float rstd = rsqrtf(var + 1e-12f);
    float4 gv = *(const float4*)(gamma + tid * 4);
    float4 bv = *(const float4*)(beta + tid * 4);
    float4 o;
    o.x = (v.x - mean) * rstd * gv.x + bv.x;
    o.y = (v.y - mean) * rstd * gv.y + bv.y;
    o.z = (v.z - mean) * rstd * gv.z + bv.z;
    o.w = (v.w - mean) * rstd * gv.w + bv.w;
    *(float4*)(r + tid * 4) = o;
}

// ---------------------------------------------------------------------------
extern "C" void kernel_launch(void* const* d_in, const int* in_sizes, int n_in,
                              void* d_out, int out_size)
{
    const float* hidden  = (const float*)d_in[0];
    const float* Wq      = (const float*)d_in[1];
    const float* bq      = (const float*)d_in[2];
    const float* Wk      = (const float*)d_in[3];
    const float* bk      = (const float*)d_in[4];
    const float* Wv      = (const float*)d_in[5];
    const float* bv      = (const float*)d_in[6];
    const float* Wo      = (const float*)d_in[7];
    const float* bo      = (const float*)d_in[8];
    const float* gamma   = (const float*)d_in[9];
    const float* beta    = (const float*)d_in[10];
    const float* dist    = (const float*)d_in[11];

    float* out   = (float*)d_out;
    float* probs = out + (size_t)BB * SS * HID;   // tuple order: (out, probs)

    cudaFuncSetAttribute(attn_kernel,
                         cudaFuncAttributeMaxDynamicSharedMemorySize, SMEM_BYTES);

    dim3 gg(8, 32);
    sgemm_qkv<<<gg, 256>>>(hidden, Wq, bq, 0);
    sgemm_qkv<<<gg, 256>>>(hidden, Wk, bk, 1);
    sgemm_qkv<<<gg, 256>>>(hidden, Wv, bv, 2);

    dim3 ga(32, 32, 4);
    attn_kernel<<<ga, 256, SMEM_BYTES>>>(dist, probs);

    sgemm_proj<<<gg, 256>>>(hidden, Wo, bo, out);
    ln_kernel<<<4096, 256>>>(out, gamma, beta);
}

// round 3
// speedup vs baseline: 2.0071x; 2.0071x over previous
#include <cuda_runtime.h>
#include <cstdint>
#include <math.h>

#define BB   4
#define SS   1024
#define HID  1024
#define NH   32
#define HD   32
#define SCALE 0.17677669529663688f   // 1/sqrt(32)

__device__ float g_q[BB * NH * SS * HD];
__device__ float g_k[BB * NH * SS * HD];
__device__ float g_v[BB * NH * SS * HD];
__device__ float g_ctx[BB * NH * SS * HD];

// ---------------------------------------------------------------------------
// tf32 mma helpers
// ---------------------------------------------------------------------------
__device__ __forceinline__ uint32_t f2t(float x) {
    uint32_t r;
    asm("cvt.rna.tf32.f32 %0, %1;" : "=r"(r) : "f"(x));
    return r;
}

__device__ __forceinline__ void mma8(float* c, const uint32_t* a, const uint32_t* b) {
    asm("mma.sync.aligned.m16n8k8.row.col.f32.tf32.tf32.f32 "
        "{%0,%1,%2,%3}, {%4,%5,%6,%7}, {%8,%9}, {%0,%1,%2,%3};"
        : "+f"(c[0]), "+f"(c[1]), "+f"(c[2]), "+f"(c[3])
        : "r"(a[0]), "r"(a[1]), "r"(a[2]), "r"(a[3]), "r"(b[0]), "r"(b[1]));
}

// ---------------------------------------------------------------------------
// tf32 GEMM: C[m,n] = sum_k A[m,k]*W[n,k] + bias[n], scatter to (b,h,s,d)
// BM=BN=128, BK=16, 256 threads (8 warps), warp tile 32x64.
// ---------------------------------------------------------------------------
#define GS 20   // smem row stride (conflict-free for fragment loads)

__global__ __launch_bounds__(256, 2) void mm_qkv(
    const float* __restrict__ A, const float* __restrict__ W,
    const float* __restrict__ bias, int sel)
{
    float* out = (sel == 0) ? g_q : (sel == 1) ? g_k : g_v;
    __shared__ float As[128 * GS];
    __shared__ float Ws[128 * GS];

    const int tid = threadIdx.x;
    const int wid = tid >> 5, lane = tid & 31;
    const int g = lane >> 2, q4 = lane & 3;
    const int wm = (wid & 3) * 32, wn = (wid >> 2) * 64;
    const int row0 = blockIdx.y * 128, col0 = blockIdx.x * 128;

    float acc[2][8][4];
#pragma unroll
    for (int i = 0; i < 2; i++)
#pragma unroll
        for (int j = 0; j < 8; j++)
#pragma unroll
            for (int z = 0; z < 4; z++) acc[i][j][z] = 0.f;

    for (int k0 = 0; k0 < 1024; k0 += 16) {
#pragma unroll
        for (int it = 0; it < 2; ++it) {
            int f = tid + it * 256;
            int r = f >> 2, c4 = (f & 3) * 4;
            *(float4*)&As[r * GS + c4] =
                *(const float4*)(A + (size_t)(row0 + r) * 1024 + k0 + c4);
            *(float4*)&Ws[r * GS + c4] =
                *(const float4*)(W + (size_t)(col0 + r) * 1024 + k0 + c4);
        }
        __syncthreads();
#pragma unroll
        for (int ks = 0; ks < 2; ++ks) {
            int kk = ks * 8;
            uint32_t a[2][4];
#pragma unroll
            for (int mt = 0; mt < 2; ++mt) {
                int m0 = wm + mt * 16;
                a[mt][0] = f2t(As[(m0 + g) * GS + kk + q4]);
                a[mt][1] = f2t(As[(m0 + g + 8) * GS + kk + q4]);
                a[mt][2] = f2t(As[(m0 + g) * GS + kk + 4 + q4]);
                a[mt][3] = f2t(As[(m0 + g + 8) * GS + kk + 4 + q4]);
            }
#pragma unroll
            for (int nt = 0; nt < 8; ++nt) {
                int n0 = wn + nt * 8;
                uint32_t b[2];
                b[0] = f2t(Ws[(n0 + g) * GS + kk + q4]);
                b[1] = f2t(Ws[(n0 + g) * GS + kk + 4 + q4]);
                mma8(acc[0][nt], a[0], b);
                mma8(acc[1][nt], a[1], b);
            }
        }
        __syncthreads();
    }

#pragma unroll
    for (int mt = 0; mt < 2; ++mt) {
#pragma unroll
        for (int nt = 0; nt < 8; ++nt) {
#pragma unroll
            for (int half = 0; half < 2; ++half) {
                int m = row0 + wm + mt * 16 + g + half * 8;
                int b_ = m >> 10, s = m & 1023;
#pragma unroll
                for (int cc = 0; cc < 2; ++cc) {
                    int n = col0 + wn + nt * 8 + q4 * 2 + cc;
                    int h = n >> 5, d = n & 31;
                    out[((((size_t)b_ * NH + h) << 10) + s) * HD + d] =
                        acc[mt][nt][half * 2 + cc] + bias[n];
                }
            }
        }
    }
}

// ---------------------------------------------------------------------------
// tf32 out-projection: out = ctx @ Wo^T + bo + hidden (pre-LN)
// ---------------------------------------------------------------------------
__global__ __launch_bounds__(256, 2) void mm_proj(
    const float* __restrict__ hidden, const float* __restrict__ Wo,
    const float* __restrict__ bo, float* __restrict__ out)
{
    __shared__ float As[128 * GS];
    __shared__ float Ws[128 * GS];

    const int tid = threadIdx.x;
    const int wid = tid >> 5, lane = tid & 31;
    const int g = lane >> 2, q4 = lane & 3;
    const int wm = (wid & 3) * 32, wn = (wid >> 2) * 64;
    const int row0 = blockIdx.y * 128, col0 = blockIdx.x * 128;

    float acc[2][8][4];
#pragma unroll
    for (int i = 0; i < 2; i++)
#pragma unroll
        for (int j = 0; j < 8; j++)
#pragma unroll
            for (int z = 0; z < 4; z++) acc[i][j][z] = 0.f;

    for (int k0 = 0; k0 < 1024; k0 += 16) {
#pragma unroll
        for (int it = 0; it < 2; ++it) {
            int f = tid + it * 256;
            int r = f >> 2, c4 = (f & 3) * 4;
            int kk0 = k0 + c4;
            int m = row0 + r;
            int b_ = m >> 10, s = m & 1023;
            int h = kk0 >> 5, dl = kk0 & 31;
            *(float4*)&As[r * GS + c4] =
                *(const float4*)(g_ctx + ((((size_t)b_ * NH + h) << 10) + s) * HD + dl);
            *(float4*)&Ws[r * GS + c4] =
                *(const float4*)(Wo + (size_t)(col0 + r) * 1024 + kk0);
        }
        __syncthreads();
#pragma unroll
        for (int ks = 0; ks < 2; ++ks) {
            int kk = ks * 8;
            uint32_t a[2][4];
#pragma unroll
            for (int mt = 0; mt < 2; ++mt) {
                int m0 = wm + mt * 16;
                a[mt][0] = f2t(As[(m0 + g) * GS + kk + q4]);
                a[mt][1] = f2t(As[(m0 + g + 8) * GS + kk + q4]);
                a[mt][2] = f2t(As[(m0 + g) * GS + kk + 4 + q4]);
                a[mt][3] = f2t(As[(m0 + g + 8) * GS + kk + 4 + q4]);
            }
#pragma unroll
            for (int nt = 0; nt < 8; ++nt) {
                int n0 = wn + nt * 8;
                uint32_t b[2];
                b[0] = f2t(Ws[(n0 + g) * GS + kk + q4]);
                b[1] = f2t(Ws[(n0 + g) * GS + kk + 4 + q4]);
                mma8(acc[0][nt], a[0], b);
                mma8(acc[1][nt], a[1], b);
            }
        }
        __syncthreads();
    }

#pragma unroll
    for (int mt = 0; mt < 2; ++mt) {
#pragma unroll
        for (int nt = 0; nt < 8; ++nt) {
#pragma unroll
            for (int half = 0; half < 2; ++half) {
                int m = row0 + wm + mt * 16 + g + half * 8;
#pragma unroll
                for (int cc = 0; cc < 2; ++cc) {
                    int n = col0 + wn + nt * 8 + q4 * 2 + cc;
                    size_t idx = (size_t)m * 1024 + n;
                    out[idx] = acc[mt][nt][half * 2 + cc] + bo[n] + hidden[idx];
                }
            }
        }
    }
}

// ---------------------------------------------------------------------------
// Fused attention (tf32 mma): block = 32 queries x (b,h).
// scores tile 32x1024 resident in smem; Q fragments resident in registers.
// ---------------------------------------------------------------------------
#define SC_STRIDE 1028
#define OFF_QS   (32 * SC_STRIDE)            // 32896
#define OFF_KV   (OFF_QS + 32 * 36)          // 34048
#define OFF_BIAS (OFF_KV + 256 * 36)         // 43264
#define OFF_PART (OFF_BIAS + 1056)           // 44320
#define A_SMEM_FLOATS (OFF_PART + 8 * 1056)  // 52768
#define A_SMEM_BYTES  (A_SMEM_FLOATS * 4)    // 211072

__global__ __launch_bounds__(256, 1) void attn_kernel(
    const float* __restrict__ dist_emb, float* __restrict__ probs_out)
{
    extern __shared__ float sm[];
    float* sc    = sm;
    float* Qs    = sm + OFF_QS;    // [q][d] stride 36
    float* KVs   = sm + OFF_KV;    // [key][d] stride 36, 256 keys
    float* biasr = sm + OFF_BIAS;  // 1055 entries
    float* part  = sm + OFF_PART;  // [8 warps][32][33]

    const int tid = threadIdx.x;
    const int wid = tid >> 5, lane = tid & 31;
    const int g = lane >> 2, q4 = lane & 3;
    const int q0 = blockIdx.x * 32;
    const int h  = blockIdx.y;
    const int b  = blockIdx.z;
    const int bh = b * NH + h;

    const float* Qg = g_q + ((size_t)bh * SS + q0) * HD;
    const float* Kg = g_k + (size_t)bh * SS * HD;
    const float* Vg = g_v + (size_t)bh * SS * HD;
    float* ctxg = g_ctx + ((size_t)bh * SS + q0) * HD;
    const size_t probs_base = ((size_t)bh * SS + q0) * SS;

    // Load Q tile [32][32] into Qs
    {
        int r = tid >> 3, c4 = (tid & 7) * 4;
        *(float4*)&Qs[r * 36 + c4] = *(const float4*)(Qg + (size_t)r * HD + c4);
    }
    for (int t = tid; t < 1055; t += 256)
        biasr[t] = dist_emb[(size_t)(q0 + t) * HD + h];
    __syncthreads();

    // Preload Q fragments (A operand) for all 4 k-steps x 2 m-tiles
    uint32_t aq[4][2][4];
#pragma unroll
    for (int ks = 0; ks < 4; ++ks) {
        int kk = ks * 8;
#pragma unroll
        for (int mt = 0; mt < 2; ++mt) {
            int m0 = mt * 16;
            aq[ks][mt][0] = f2t(Qs[(m0 + g) * 36 + kk + q4]);
            aq[ks][mt][1] = f2t(Qs[(m0 + g + 8) * 36 + kk + q4]);
            aq[ks][mt][2] = f2t(Qs[(m0 + g) * 36 + kk + 4 + q4]);
            aq[ks][mt][3] = f2t(Qs[(m0 + g + 8) * 36 + kk + 4 + q4]);
        }
    }

    // ---- Phase A: scores = (Q K^T + bias) * SCALE -> sc ----
    const int kb = wid * 32;   // warp's 32 keys within a 256-key chunk
    for (int kc = 0; kc < 4; ++kc) {
#pragma unroll
        for (int it = 0; it < 8; ++it) {
            int f = tid + it * 256;        // 2048 float4
            int key = f >> 3, c4 = (f & 7) * 4;
            *(float4*)&KVs[key * 36 + c4] =
                *(const float4*)(Kg + ((size_t)kc * 256 + key) * HD + c4);
        }
        __syncthreads();

        float accs[2][4][4];
#pragma unroll
        for (int i = 0; i < 2; i++)
#pragma unroll
            for (int j = 0; j < 4; j++)
#pragma unroll
                for (int z = 0; z < 4; z++) accs[i][j][z] = 0.f;

#pragma unroll
        for (int ks = 0; ks < 4; ++ks) {
            int kk = ks * 8;
#pragma unroll
            for (int nt = 0; nt < 4; ++nt) {
                int n0 = kb + nt * 8;
                uint32_t bfr[2];
                bfr[0] = f2t(KVs[(n0 + g) * 36 + kk + q4]);
                bfr[1] = f2t(KVs[(n0 + g) * 36 + kk + 4 + q4]);
                mma8(accs[0][nt], aq[ks][0], bfr);
                mma8(accs[1][nt], aq[ks][1], bfr);
            }
        }

        int gcol = kc * 256 + kb;
#pragma unroll
        for (int mt = 0; mt < 2; ++mt) {
#pragma unroll
            for (int nt = 0; nt < 4; ++nt) {
#pragma unroll
                for (int half = 0; half < 2; ++half) {
                    int qr = mt * 16 + g + half * 8;
#pragma unroll
                    for (int cc = 0; cc < 2; ++cc) {
                        int col = gcol + nt * 8 + q4 * 2 + cc;
                        sc[qr * SC_STRIDE + col] =
                            (accs[mt][nt][half * 2 + cc] + biasr[qr - col + 1023]) * SCALE;
                    }
                }
            }
        }
        __syncthreads();
    }

    // ---- Softmax + probs write ----
    {
        int w = tid >> 5, l = tid & 31;
#pragma unroll
        for (int qi = 0; qi < 4; ++qi) {
            int q = w + 8 * qi;
            float* row = sc + q * SC_STRIDE;
            float m = -1e30f;
#pragma unroll
            for (int j = 0; j < 32; j++) m = fmaxf(m, row[l + 32 * j]);
#pragma unroll
            for (int off = 16; off > 0; off >>= 1)
                m = fmaxf(m, __shfl_xor_sync(0xffffffffu, m, off));
            float s = 0.f;
#pragma unroll
            for (int j = 0; j < 32; j++) {
                float e = __expf(row[l + 32 * j] - m);
                row[l + 32 * j] = e;
                s += e;
            }
#pragma unroll
            for (int off = 16; off > 0; off >>= 1)
                s += __shfl_xor_sync(0xffffffffu, s, off);
            float inv = 1.f / s;
            float* pg = probs_out + probs_base + (size_t)q * SS;
#pragma unroll
            for (int j = 0; j < 32; j++) {
                float p = row[l + 32 * j] * inv;
                row[l + 32 * j] = p;
                pg[l + 32 * j] = p;
            }
        }
    }
    __syncthreads();

    // ---- Phase B: ctx = P @ V (warp split-k, 128 keys per warp) ----
    {
        float accv[2][4][4];
#pragma unroll
        for (int i = 0; i < 2; i++)
#pragma unroll
            for (int j = 0; j < 4; j++)
#pragma unroll
                for (int z = 0; z < 4; z++) accv[i][j][z] = 0.f;

        for (int kc = 0; kc < 4; ++kc) {
#pragma unroll
            for (int it = 0; it < 8; ++it) {
                int f = tid + it * 256;
                int key = f >> 3, c4 = (f & 7) * 4;
                *(float4*)&KVs[key * 36 + c4] =
                    *(const float4*)(Vg + ((size_t)kc * 256 + key) * HD + c4);
            }
            __syncthreads();

#pragma unroll
            for (int ks = 0; ks < 4; ++ks) {
                int klocal = kb + ks * 8;          // key base within chunk
                int kglob = kc * 256 + klocal;     // global key base
                uint32_t ap[2][4];
#pragma unroll
                for (int mt = 0; mt < 2; ++mt) {
                    int m0 = mt * 16;
                    ap[mt][0] = f2t(sc[(m0 + g) * SC_STRIDE + kglob + q4]);
                    ap[mt][1] = f2t(sc[(m0 + g + 8) * SC_STRIDE + kglob + q4]);
                    ap[mt][2] = f2t(sc[(m0 + g) * SC_STRIDE + kglob + 4 + q4]);
                    ap[mt][3] = f2t(sc[(m0 + g + 8) * SC_STRIDE + kglob + 4 + q4]);
                }
#pragma unroll
                for (int nt = 0; nt < 4; ++nt) {
                    int n0 = nt * 8;
                    uint32_t bfr[2];
                    bfr[0] = f2t(KVs[(klocal + q4) * 36 + n0 + g]);
                    bfr[1] = f2t(KVs[(klocal + 4 + q4) * 36 + n0 + g]);
                    mma8(accv[0][nt], ap[0], bfr);
                    mma8(accv[1][nt], ap[1], bfr);
                }
            }
            __syncthreads();
        }

        // write warp partials
#pragma unroll
        for (int mt = 0; mt < 2; ++mt) {
#pragma unroll
            for (int nt = 0; nt < 4; ++nt) {
#pragma unroll
                for (int half = 0; half < 2; ++half) {
                    int qr = mt * 16 + g + half * 8;
#pragma unroll
                    for (int cc = 0; cc < 2; ++cc) {
                        int d = nt * 8 + q4 * 2 + cc;
                        part[wid * 1056 + qr * 33 + d] = accv[mt][nt][half * 2 + cc];
                    }
                }
            }
        }
        __syncthreads();

#pragma unroll
        for (int z = 0; z < 4; z++) {
            int o = tid * 4 + z;
            int qr = o >> 5, d = o & 31;
            float sum = 0.f;
#pragma unroll
            for (int w = 0; w < 8; w++) sum += part[w * 1056 + qr * 33 + d];
            ctxg[o] = sum;
        }
    }
}

// ---------------------------------------------------------------------------
// LayerNorm in place (4096 rows x 1024)
// ---------------------------------------------------------------------------
__global__ __launch_bounds__(256) void ln_kernel(
    float* __restrict__ x, const float* __restrict__ gamma,
    const float* __restrict__ beta)
{
    __shared__ float red[16];
    const int row = blockIdx.x;
    const int tid = threadIdx.x;
    float* r = x + (size_t)row * 1024;
    float4 v = *(float4*)(r + tid * 4);
    float s = v.x + v.y + v.z + v.w;
    float sq = v.x * v.x + v.y * v.y + v.z * v.z + v.w * v.w;
#pragma unroll
    for (int off = 16; off > 0; off >>= 1) {
        s  += __shfl_xor_sync(0xffffffffu, s, off);
        sq += __shfl_xor_sync(0xffffffffu, sq, off);
    }
    int w = tid >> 5, l = tid & 31;
    if (l == 0) { red[w] = s; red[8 + w] = sq; }
    __syncthreads();
    if (tid < 32) {
        float a = (tid < 8) ? red[tid] : 0.f;
        float bsq = (tid < 8) ? red[8 + tid] : 0.f;
#pragma unroll
        for (int off = 4; off > 0; off >>= 1) {
            a += __shfl_xor_sync(0xffffffffu, a, off);
            bsq += __shfl_xor_sync(0xffffffffu, bsq, off);
        }
        if (tid == 0) { red[0] = a; red[8] = bsq; }
    }
    __syncthreads();
    float mean = red[0] * (1.f / 1024.f);
    float var = red[8] * (1.f / 1024.f) - mean * mean;
    float rstd = rsqrtf(var + 1e-12f);
    float4 gv = *(const float4*)(gamma + tid * 4);
    float4 bv = *(const float4*)(beta + tid * 4);
    float4 o;
    o.x = (v.x - mean) * rstd * gv.x + bv.x;
    o.y = (v.y - mean) * rstd * gv.y + bv.y;
    o.z = (v.z - mean) * rstd * gv.z + bv.z;
    o.w = (v.w - mean) * rstd * gv.w + bv.w;
    *(float4*)(r + tid * 4) = o;
}

// ---------------------------------------------------------------------------
extern "C" void kernel_launch(void* const* d_in, const int* in_sizes, int n_in,
                              void* d_out, int out_size)
{
    const float* hidden  = (const float*)d_in[0];
    const float* Wq      = (const float*)d_in[1];
    const float* bq      = (const float*)d_in[2];
    const float* Wk      = (const float*)d_in[3];
    const float* bk      = (const float*)d_in[4];
    const float* Wv      = (const float*)d_in[5];
    const float* bv      = (const float*)d_in[6];
    const float* Wo      = (const float*)d_in[7];
    const float* bo      = (const float*)d_in[8];
    const float* gamma   = (const float*)d_in[9];
    const float* beta    = (const float*)d_in[10];
    const float* dist    = (const float*)d_in[11];

    float* out   = (float*)d_out;
    float* probs = out + (size_t)BB * SS * HID;

    cudaFuncSetAttribute(attn_kernel,
                         cudaFuncAttributeMaxDynamicSharedMemorySize, A_SMEM_BYTES);

    dim3 gg(8, 32);
    mm_qkv<<<gg, 256>>>(hidden, Wq, bq, 0);
    mm_qkv<<<gg, 256>>>(hidden, Wk, bk, 1);
    mm_qkv<<<gg, 256>>>(hidden, Wv, bv, 2);

    dim3 ga(32, 32, 4);
    attn_kernel<<<ga, 256, A_SMEM_BYTES>>>(dist, probs);

    mm_proj<<<gg, 256>>>(hidden, Wo, bo, out);
    ln_kernel<<<4096, 256>>>(out, gamma, beta);
}

// round 4
// speedup vs baseline: 2.3924x; 1.1920x over previous
#include <cuda_runtime.h>
#include <cstdint>
#include <math.h>

#define BB   4
#define SS   1024
#define HID  1024
#define NH   32
#define HD   32
#define SCALE 0.17677669529663688f   // 1/sqrt(32)

__device__ float g_q[BB * NH * SS * HD];
__device__ float g_k[BB * NH * SS * HD];
__device__ float g_v[BB * NH * SS * HD];
__device__ float g_ctx[BB * NH * SS * HD];

// ---------------------------------------------------------------------------
// helpers
// ---------------------------------------------------------------------------
__device__ __forceinline__ uint32_t f2t(float x) {
    uint32_t r;
    asm("cvt.rna.tf32.f32 %0, %1;" : "=r"(r) : "f"(x));
    return r;
}

__device__ __forceinline__ void mma8(float* c, const uint32_t* a, const uint32_t* b) {
    asm("mma.sync.aligned.m16n8k8.row.col.f32.tf32.tf32.f32 "
        "{%0,%1,%2,%3}, {%4,%5,%6,%7}, {%8,%9}, {%0,%1,%2,%3};"
        : "+f"(c[0]), "+f"(c[1]), "+f"(c[2]), "+f"(c[3])
        : "r"(a[0]), "r"(a[1]), "r"(a[2]), "r"(a[3]), "r"(b[0]), "r"(b[1]));
}

// ---------------------------------------------------------------------------
// tf32 GEMM (QKV fused over blockIdx.z): C = A @ W^T + bias -> (b,h,s,d)
// BM=BN=128, BK=16, 256 threads, warp tile 32x64.
// ---------------------------------------------------------------------------
#define GS 20

__global__ __launch_bounds__(256, 2) void mm_qkv(
    const float* __restrict__ A,
    const float* __restrict__ Wq, const float* __restrict__ Wk,
    const float* __restrict__ Wv,
    const float* __restrict__ bq, const float* __restrict__ bk,
    const float* __restrict__ bv)
{
    const int sel = blockIdx.z;
    const float* W = (sel == 0) ? Wq : (sel == 1) ? Wk : Wv;
    const float* bias = (sel == 0) ? bq : (sel == 1) ? bk : bv;
    float* out = (sel == 0) ? g_q : (sel == 1) ? g_k : g_v;

    __shared__ float As[128 * GS];
    __shared__ float Ws[128 * GS];

    const int tid = threadIdx.x;
    const int wid = tid >> 5, lane = tid & 31;
    const int g = lane >> 2, q4 = lane & 3;
    const int wm = (wid & 3) * 32, wn = (wid >> 2) * 64;
    const int row0 = blockIdx.y * 128, col0 = blockIdx.x * 128;

    float acc[2][8][4];
#pragma unroll
    for (int i = 0; i < 2; i++)
#pragma unroll
        for (int j = 0; j < 8; j++)
#pragma unroll
            for (int z = 0; z < 4; z++) acc[i][j][z] = 0.f;

    for (int k0 = 0; k0 < 1024; k0 += 16) {
#pragma unroll
        for (int it = 0; it < 2; ++it) {
            int f = tid + it * 256;
            int r = f >> 2, c4 = (f & 3) * 4;
            *(float4*)&As[r * GS + c4] =
                *(const float4*)(A + (size_t)(row0 + r) * 1024 + k0 + c4);
            *(float4*)&Ws[r * GS + c4] =
                *(const float4*)(W + (size_t)(col0 + r) * 1024 + k0 + c4);
        }
        __syncthreads();
#pragma unroll
        for (int ks = 0; ks < 2; ++ks) {
            int kk = ks * 8;
            uint32_t a[2][4];
#pragma unroll
            for (int mt = 0; mt < 2; ++mt) {
                int m0 = wm + mt * 16;
                a[mt][0] = f2t(As[(m0 + g) * GS + kk + q4]);
                a[mt][1] = f2t(As[(m0 + g + 8) * GS + kk + q4]);
                a[mt][2] = f2t(As[(m0 + g) * GS + kk + 4 + q4]);
                a[mt][3] = f2t(As[(m0 + g + 8) * GS + kk + 4 + q4]);
            }
#pragma unroll
            for (int nt = 0; nt < 8; ++nt) {
                int n0 = wn + nt * 8;
                uint32_t b[2];
                b[0] = f2t(Ws[(n0 + g) * GS + kk + q4]);
                b[1] = f2t(Ws[(n0 + g) * GS + kk + 4 + q4]);
                mma8(acc[0][nt], a[0], b);
                mma8(acc[1][nt], a[1], b);
            }
        }
        __syncthreads();
    }

#pragma unroll
    for (int mt = 0; mt < 2; ++mt) {
#pragma unroll
        for (int nt = 0; nt < 8; ++nt) {
#pragma unroll
            for (int half = 0; half < 2; ++half) {
                int m = row0 + wm + mt * 16 + g + half * 8;
                int b_ = m >> 10, s = m & 1023;
#pragma unroll
                for (int cc = 0; cc < 2; ++cc) {
                    int n = col0 + wn + nt * 8 + q4 * 2 + cc;
                    int h = n >> 5, d = n & 31;
                    out[((((size_t)b_ * NH + h) << 10) + s) * HD + d] =
                        acc[mt][nt][half * 2 + cc] + bias[n];
                }
            }
        }
    }
}

// ---------------------------------------------------------------------------
// tf32 out-projection: out = ctx @ Wo^T + bo + hidden (pre-LN)
// ---------------------------------------------------------------------------
__global__ __launch_bounds__(256, 2) void mm_proj(
    const float* __restrict__ hidden, const float* __restrict__ Wo,
    const float* __restrict__ bo, float* __restrict__ out)
{
    __shared__ float As[128 * GS];
    __shared__ float Ws[128 * GS];

    const int tid = threadIdx.x;
    const int wid = tid >> 5, lane = tid & 31;
    const int g = lane >> 2, q4 = lane & 3;
    const int wm = (wid & 3) * 32, wn = (wid >> 2) * 64;
    const int row0 = blockIdx.y * 128, col0 = blockIdx.x * 128;

    float acc[2][8][4];
#pragma unroll
    for (int i = 0; i < 2; i++)
#pragma unroll
        for (int j = 0; j < 8; j++)
#pragma unroll
            for (int z = 0; z < 4; z++) acc[i][j][z] = 0.f;

    for (int k0 = 0; k0 < 1024; k0 += 16) {
#pragma unroll
        for (int it = 0; it < 2; ++it) {
            int f = tid + it * 256;
            int r = f >> 2, c4 = (f & 3) * 4;
            int kk0 = k0 + c4;
            int m = row0 + r;
            int b_ = m >> 10, s = m & 1023;
            int h = kk0 >> 5, dl = kk0 & 31;
            *(float4*)&As[r * GS + c4] =
                *(const float4*)(g_ctx + ((((size_t)b_ * NH + h) << 10) + s) * HD + dl);
            *(float4*)&Ws[r * GS + c4] =
                *(const float4*)(Wo + (size_t)(col0 + r) * 1024 + kk0);
        }
        __syncthreads();
#pragma unroll
        for (int ks = 0; ks < 2; ++ks) {
            int kk = ks * 8;
            uint32_t a[2][4];
#pragma unroll
            for (int mt = 0; mt < 2; ++mt) {
                int m0 = wm + mt * 16;
                a[mt][0] = f2t(As[(m0 + g) * GS + kk + q4]);
                a[mt][1] = f2t(As[(m0 + g + 8) * GS + kk + q4]);
                a[mt][2] = f2t(As[(m0 + g) * GS + kk + 4 + q4]);
                a[mt][3] = f2t(As[(m0 + g + 8) * GS + kk + 4 + q4]);
            }
#pragma unroll
            for (int nt = 0; nt < 8; ++nt) {
                int n0 = wn + nt * 8;
                uint32_t b[2];
                b[0] = f2t(Ws[(n0 + g) * GS + kk + q4]);
                b[1] = f2t(Ws[(n0 + g) * GS + kk + 4 + q4]);
                mma8(acc[0][nt], a[0], b);
                mma8(acc[1][nt], a[1], b);
            }
        }
        __syncthreads();
    }

#pragma unroll
    for (int mt = 0; mt < 2; ++mt) {
#pragma unroll
        for (int nt = 0; nt < 8; ++nt) {
#pragma unroll
            for (int half = 0; half < 2; ++half) {
                int m = row0 + wm + mt * 16 + g + half * 8;
#pragma unroll
                for (int cc = 0; cc < 2; ++cc) {
                    int n = col0 + wn + nt * 8 + q4 * 2 + cc;
                    size_t idx = (size_t)m * 1024 + n;
                    out[idx] = acc[mt][nt][half * 2 + cc] + bo[n] + hidden[idx];
                }
            }
        }
    }
}

// ---------------------------------------------------------------------------
// Fused attention, 512 threads, cp.async double-buffered K/V.
// ---------------------------------------------------------------------------
#define SC_STRIDE 1028
#define OFF_QS   (32 * SC_STRIDE)            // 32896
#define OFF_BIAS (OFF_QS + 32 * 36)          // 34048
#define OFF_KV   (OFF_BIAS + 1056)           // 35104
#define KV_BUF   (256 * 36)                  // 9216 floats per buffer
#define A_SMEM_FLOATS (OFF_KV + 2 * KV_BUF)  // 53536
#define A_SMEM_BYTES  (A_SMEM_FLOATS * 4)    // 214144

__device__ __forceinline__ void load_chunk256(
    uint32_t kv_base_bytes, int buf, const float* __restrict__ src,
    int kc, int tid)
{
#pragma unroll
    for (int it = 0; it < 4; ++it) {
        int f = tid + it * 512;          // 2048 x 16B
        int key = f >> 3, c4 = (f & 7) * 4;
        uint32_t dst = kv_base_bytes + (uint32_t)(buf * KV_BUF + key * 36 + c4) * 4u;
        asm volatile("cp.async.cg.shared.global [%0], [%1], 16;" ::
            "r"(dst), "l"(src + (size_t)kc * 256 * 32 + key * 32 + c4));
    }
    asm volatile("cp.async.commit_group;");
}

__global__ __launch_bounds__(512, 1) void attn_kernel(
    const float* __restrict__ dist_emb, float* __restrict__ probs_out)
{
    extern __shared__ float sm[];
    float* sc    = sm;
    float* Qs    = sm + OFF_QS;
    float* biasr = sm + OFF_BIAS;
    float* KV0   = sm + OFF_KV;
    float* part  = sm + OFF_KV;   // alias buffer 0 (dead by the time partials land)

    const int tid = threadIdx.x;
    const int wid = tid >> 5, lane = tid & 31;
    const int g = lane >> 2, q4 = lane & 3;
    const int q0 = blockIdx.x * 32;
    const int h  = blockIdx.y;
    const int b  = blockIdx.z;
    const int bh = b * NH + h;

    const float* Qg = g_q + ((size_t)bh * SS + q0) * HD;
    const float* Kg = g_k + (size_t)bh * SS * HD;
    const float* Vg = g_v + (size_t)bh * SS * HD;
    float* ctxg = g_ctx + ((size_t)bh * SS + q0) * HD;
    const size_t probs_base = ((size_t)bh * SS + q0) * SS;

    const uint32_t kv_base_bytes =
        (uint32_t)__cvta_generic_to_shared(KV0);

    // Q tile + bias row (plain loads) ; kick off K chunks 0,1 (cp.async)
    if (tid < 256) {
        int r = tid >> 3, c4 = (tid & 7) * 4;
        *(float4*)&Qs[r * 36 + c4] = *(const float4*)(Qg + (size_t)r * HD + c4);
    }
    for (int t = tid; t < 1055; t += 512)
        biasr[t] = dist_emb[(size_t)(q0 + t) * HD + h];

    load_chunk256(kv_base_bytes, 0, Kg, 0, tid);
    load_chunk256(kv_base_bytes, 1, Kg, 1, tid);
    __syncthreads();

    // Q fragments resident in registers
    uint32_t aq[4][2][4];
#pragma unroll
    for (int ks = 0; ks < 4; ++ks) {
        int kk = ks * 8;
#pragma unroll
        for (int mt = 0; mt < 2; ++mt) {
            int m0 = mt * 16;
            aq[ks][mt][0] = f2t(Qs[(m0 + g) * 36 + kk + q4]);
            aq[ks][mt][1] = f2t(Qs[(m0 + g + 8) * 36 + kk + q4]);
            aq[ks][mt][2] = f2t(Qs[(m0 + g) * 36 + kk + 4 + q4]);
            aq[ks][mt][3] = f2t(Qs[(m0 + g + 8) * 36 + kk + 4 + q4]);
        }
    }

    // ---- Phase A: scores ----
    const int kb = wid * 16;     // warp's 16 keys within a 256-key chunk
    for (int kc = 0; kc < 4; ++kc) {
        if (kc < 3) asm volatile("cp.async.wait_group 1;");
        else        asm volatile("cp.async.wait_group 0;");
        __syncthreads();

        const float* KVc = KV0 + (kc & 1) * KV_BUF;
        float accs[2][2][4];
#pragma unroll
        for (int i = 0; i < 2; i++)
#pragma unroll
            for (int j = 0; j < 2; j++)
#pragma unroll
                for (int z = 0; z < 4; z++) accs[i][j][z] = 0.f;

#pragma unroll
        for (int ks = 0; ks < 4; ++ks) {
            int kk = ks * 8;
#pragma unroll
            for (int nt = 0; nt < 2; ++nt) {
                int n0 = kb + nt * 8;
                uint32_t bfr[2];
                bfr[0] = f2t(KVc[(n0 + g) * 36 + kk + q4]);
                bfr[1] = f2t(KVc[(n0 + g) * 36 + kk + 4 + q4]);
                mma8(accs[0][nt], aq[ks][0], bfr);
                mma8(accs[1][nt], aq[ks][1], bfr);
            }
        }

        int gcol = kc * 256 + kb;
#pragma unroll
        for (int mt = 0; mt < 2; ++mt) {
#pragma unroll
            for (int nt = 0; nt < 2; ++nt) {
#pragma unroll
                for (int half = 0; half < 2; ++half) {
                    int qr = mt * 16 + g + half * 8;
#pragma unroll
                    for (int cc = 0; cc < 2; ++cc) {
                        int col = gcol + nt * 8 + q4 * 2 + cc;
                        sc[qr * SC_STRIDE + col] =
                            (accs[mt][nt][half * 2 + cc] + biasr[qr - col + 1023]) * SCALE;
                    }
                }
            }
        }
        __syncthreads();
        if (kc + 2 < 4) load_chunk256(kv_base_bytes, kc & 1, Kg, kc + 2, tid);
    }

    // kick off V chunks 0,1 — they overlap with softmax below
    load_chunk256(kv_base_bytes, 0, Vg, 0, tid);
    load_chunk256(kv_base_bytes, 1, Vg, 1, tid);

    // ---- Softmax + probs write (16 warps x 2 rows) ----
    {
        int l = lane;
#pragma unroll
        for (int qi = 0; qi < 2; ++qi) {
            int q = wid + 16 * qi;
            float* row = sc + q * SC_STRIDE;
            float m = -1e30f;
#pragma unroll
            for (int j = 0; j < 32; j++) m = fmaxf(m, row[l + 32 * j]);
#pragma unroll
            for (int off = 16; off > 0; off >>= 1)
                m = fmaxf(m, __shfl_xor_sync(0xffffffffu, m, off));
            float s = 0.f;
#pragma unroll
            for (int j = 0; j < 32; j++) {
                float e = __expf(row[l + 32 * j] - m);
                row[l + 32 * j] = e;
                s += e;
            }
#pragma unroll
            for (int off = 16; off > 0; off >>= 1)
                s += __shfl_xor_sync(0xffffffffu, s, off);
            float inv = 1.f / s;
            float* pg = probs_out + probs_base + (size_t)q * SS;
#pragma unroll
            for (int j = 0; j < 32; j++) {
                float p = row[l + 32 * j] * inv;
                row[l + 32 * j] = p;
                pg[l + 32 * j] = p;
            }
        }
    }
    __syncthreads();

    // ---- Phase B: ctx = P @ V (16-way warp split-k: 64 keys per warp) ----
    {
        float accv[2][4][4];
#pragma unroll
        for (int i = 0; i < 2; i++)
#pragma unroll
            for (int j = 0; j < 4; j++)
#pragma unroll
                for (int z = 0; z < 4; z++) accv[i][j][z] = 0.f;

        for (int kc = 0; kc < 4; ++kc) {
            if (kc < 3) asm volatile("cp.async.wait_group 1;");
            else        asm volatile("cp.async.wait_group 0;");
            __syncthreads();

            const float* KVc = KV0 + (kc & 1) * KV_BUF;
#pragma unroll
            for (int ks = 0; ks < 2; ++ks) {
                int klocal = kb + ks * 8;
                int kglob = kc * 256 + klocal;
                uint32_t ap[2][4];
#pragma unroll
                for (int mt = 0; mt < 2; ++mt) {
                    int m0 = mt * 16;
                    ap[mt][0] = f2t(sc[(m0 + g) * SC_STRIDE + kglob + q4]);
                    ap[mt][1] = f2t(sc[(m0 + g + 8) * SC_STRIDE + kglob + q4]);
                    ap[mt][2] = f2t(sc[(m0 + g) * SC_STRIDE + kglob + 4 + q4]);
                    ap[mt][3] = f2t(sc[(m0 + g + 8) * SC_STRIDE + kglob + 4 + q4]);
                }
#pragma unroll
                for (int nt = 0; nt < 4; ++nt) {
                    int n0 = nt * 8;
                    uint32_t bfr[2];
                    bfr[0] = f2t(KVc[(klocal + q4) * 36 + n0 + g]);
                    bfr[1] = f2t(KVc[(klocal + 4 + q4) * 36 + n0 + g]);
                    mma8(accv[0][nt], ap[0], bfr);
                    mma8(accv[1][nt], ap[1], bfr);
                }
            }
            __syncthreads();
            if (kc + 2 < 4) load_chunk256(kv_base_bytes, kc & 1, Vg, kc + 2, tid);
        }

        // two-stage partial reduction: warps 0-7 write, 8-15 accumulate
        if (wid < 8) {
#pragma unroll
            for (int mt = 0; mt < 2; ++mt)
#pragma unroll
                for (int nt = 0; nt < 4; ++nt)
#pragma unroll
                    for (int half = 0; half < 2; ++half) {
                        int qr = mt * 16 + g + half * 8;
#pragma unroll
                        for (int cc = 0; cc < 2; ++cc) {
                            int d = nt * 8 + q4 * 2 + cc;
                            part[wid * 1056 + qr * 33 + d] = accv[mt][nt][half * 2 + cc];
                        }
                    }
        }
        __syncthreads();
        if (wid >= 8) {
#pragma unroll
            for (int mt = 0; mt < 2; ++mt)
#pragma unroll
                for (int nt = 0; nt < 4; ++nt)
#pragma unroll
                    for (int half = 0; half < 2; ++half) {
                        int qr = mt * 16 + g + half * 8;
#pragma unroll
                        for (int cc = 0; cc < 2; ++cc) {
                            int d = nt * 8 + q4 * 2 + cc;
                            part[(wid - 8) * 1056 + qr * 33 + d] += accv[mt][nt][half * 2 + cc];
                        }
                    }
        }
        __syncthreads();

#pragma unroll
        for (int z = 0; z < 2; z++) {
            int o = tid * 2 + z;
            int qr = o >> 5, d = o & 31;
            float sum = 0.f;
#pragma unroll
            for (int w = 0; w < 8; w++) sum += part[w * 1056 + qr * 33 + d];
            ctxg[o] = sum;
        }
    }
}

// ---------------------------------------------------------------------------
// LayerNorm in place (4096 rows x 1024)
// ---------------------------------------------------------------------------
__global__ __launch_bounds__(256) void ln_kernel(
    float* __restrict__ x, const float* __restrict__ gamma,
    const float* __restrict__ beta)
{
    __shared__ float red[16];
    const int row = blockIdx.x;
    const int tid = threadIdx.x;
    float* r = x + (size_t)row * 1024;
    float4 v = *(float4*)(r + tid * 4);
    float s = v.x + v.y + v.z + v.w;
    float sq = v.x * v.x + v.y * v.y + v.z * v.z + v.w * v.w;
#pragma unroll
    for (int off = 16; off > 0; off >>= 1) {
        s  += __shfl_xor_sync(0xffffffffu, s, off);
        sq += __shfl_xor_sync(0xffffffffu, sq, off);
    }
    int w = tid >> 5, l = tid & 31;
    if (l == 0) { red[w] = s; red[8 + w] = sq; }
    __syncthreads();
    if (tid < 32) {
        float a = (tid < 8) ? red[tid] : 0.f;
        float bsq = (tid < 8) ? red[8 + tid] : 0.f;
#pragma unroll
        for (int off = 4; off > 0; off >>= 1) {
            a += __shfl_xor_sync(0xffffffffu, a, off);
            bsq += __shfl_xor_sync(0xffffffffu, bsq, off);
        }
        if (tid == 0) { red[0] = a; red[8] = bsq; }
    }
    __syncthreads();
    float mean = red[0] * (1.f / 1024.f);
    float var = red[8] * (1.f / 1024.f) - mean * mean;
    float rstd = rsqrtf(var + 1e-12f);
    float4 gv = *(const float4*)(gamma + tid * 4);
    float4 bv = *(const float4*)(beta + tid * 4);
    float4 o;
    o.x = (v.x - mean) * rstd * gv.x + bv.x;
    o.y = (v.y - mean) * rstd * gv.y + bv.y;
    o.z = (v.z - mean) * rstd * gv.z + bv.z;
    o.w = (v.w - mean) * rstd * gv.w + bv.w;
    *(float4*)(r + tid * 4) = o;
}

// ---------------------------------------------------------------------------
extern "C" void kernel_launch(void* const* d_in, const int* in_sizes, int n_in,
                              void* d_out, int out_size)
{
    const float* hidden  = (const float*)d_in[0];
    const float* Wq      = (const float*)d_in[1];
    const float* bq      = (const float*)d_in[2];
    const float* Wk      = (const float*)d_in[3];
    const float* bk      = (const float*)d_in[4];
    const float* Wv      = (const float*)d_in[5];
    const float* bv      = (const float*)d_in[6];
    const float* Wo      = (const float*)d_in[7];
    const float* bo      = (const float*)d_in[8];
    const float* gamma   = (const float*)d_in[9];
    const float* beta    = (const float*)d_in[10];
    const float* dist    = (const float*)d_in[11];

    float* out   = (float*)d_out;
    float* probs = out + (size_t)BB * SS * HID;

    cudaFuncSetAttribute(attn_kernel,
                         cudaFuncAttributeMaxDynamicSharedMemorySize, A_SMEM_BYTES);

    dim3 gq(8, 32, 3);
    mm_qkv<<<gq, 256>>>(hidden, Wq, Wk, Wv, bq, bk, bv);

    dim3 ga(32, 32, 4);
    attn_kernel<<<ga, 512, A_SMEM_BYTES>>>(dist, probs);

    dim3 gg(8, 32);
    mm_proj<<<gg, 256>>>(hidden, Wo, bo, out);
    ln_kernel<<<4096, 256>>>(out, gamma, beta);
}